// round 12
// baseline (speedup 1.0000x reference)
#include <cuda_runtime.h>
#include <math.h>

#define BATCH 65536
#define IN_F  2048
#define GROUP 256
#define VEC_ROW (IN_F / 4)        // 512 float4 per row
#define KSTEPS  (VEC_ROW / 32)    // 16 float4 per lane per row
#define NSM 152
#define CHUNK 2                   // rows per work unit
#define NCHUNKS (BATCH / CHUNK)   // 32768
#define PF 2                      // prefetch distance (3-stage pipeline)
#define NGROUPS (BATCH / GROUP)   // 256

// Global work-stealing counter (zero-initialized; reset by init_heads each
// launch, which is stream-ordered before gemv_phase1).
__device__ unsigned g_ctr;

// float atomic max via signed/unsigned ordering trick (valid for all finite
// floats and -inf init): non-negative -> int max; negative -> uint min.
__device__ __forceinline__ void atomicMaxFloat(float* addr, float v)
{
    if (v >= 0.0f) atomicMax((int*)addr, __float_as_int(v));
    else           atomicMin((unsigned int*)addr, __float_as_uint(v));
}

// -------- Phase 0: init group heads to -inf + reset steal counter ----------
__global__ __launch_bounds__(NGROUPS)
void init_heads(float* __restrict__ out)
{
    out[threadIdx.x * GROUP] = -INFINITY;
    if (threadIdx.x == 0) g_ctr = 0u;
}

// ---------------- Phase 1: work-stealing GEMV + GELU + atomic group max ----
// Each warp pulls 2-row units from g_ctr. The steal for unit n+1 is issued
// before unit n's compute, so the ~320-cycle atomic latency is hidden.
__global__ __launch_bounds__(1024, 1)
void gemv_phase1(const float* __restrict__ x,
                 const float* __restrict__ w,
                 const float* __restrict__ bias,
                 float* __restrict__ out)
{
    __shared__ float4 sw[VEC_ROW];   // 8 KB weight cache

    const int tid  = threadIdx.x;
    const int lane = tid & 31;

    if (tid < VEC_ROW) sw[tid] = reinterpret_cast<const float4*>(w)[tid];
    __syncthreads();

    const float b = bias[0];

    // First steal.
    unsigned u = 0xFFFFFFFFu;
    if (lane == 0) u = atomicAdd(&g_ctr, 1u);
    u = __shfl_sync(0xFFFFFFFFu, u, 0);

    while (u < NCHUNKS) {
        // Issue the NEXT steal now; consume its result after the compute.
        unsigned unext = 0xFFFFFFFFu;
        if (lane == 0) unext = atomicAdd(&g_ctr, 1u);

        const int row0 = (int)u * CHUNK;
        const float4* __restrict__ xb =
            reinterpret_cast<const float4*>(x + (size_t)row0 * IN_F) + lane;

        float s0 = 0.f, s1 = 0.f;

        // 3-stage software pipeline over 2 rows: ~6 LDG.128 in flight/warp.
        float4 buf[PF + 1][2];
        #pragma unroll
        for (int p = 0; p < PF; p++) {
            const int off = p * 32;
            buf[p][0] = __ldcs(xb + off);
            buf[p][1] = __ldcs(xb + off + VEC_ROW);
        }

        #pragma unroll
        for (int i = 0; i < KSTEPS; i++) {
            if (i + PF < KSTEPS) {
                const int off = (i + PF) * 32;
                const int st  = (i + PF) % (PF + 1);
                buf[st][0] = __ldcs(xb + off);
                buf[st][1] = __ldcs(xb + off + VEC_ROW);
            }
            const int cu = i % (PF + 1);
            float4 wv = sw[lane + i * 32];
            s0 = fmaf(buf[cu][0].x, wv.x, s0); s0 = fmaf(buf[cu][0].y, wv.y, s0);
            s0 = fmaf(buf[cu][0].z, wv.z, s0); s0 = fmaf(buf[cu][0].w, wv.w, s0);
            s1 = fmaf(buf[cu][1].x, wv.x, s1); s1 = fmaf(buf[cu][1].y, wv.y, s1);
            s1 = fmaf(buf[cu][1].z, wv.z, s1); s1 = fmaf(buf[cu][1].w, wv.w, s1);
        }

        // 2 interleaved butterfly all-reduces.
        #pragma unroll
        for (int o = 16; o > 0; o >>= 1) {
            s0 += __shfl_xor_sync(0xFFFFFFFFu, s0, o);
            s1 += __shfl_xor_sync(0xFFFFFFFFu, s1, o);
        }

        // Epilogue: lanes 0..1 compute the 2 row GELUs; zero-fill non-head
        // rows; one atomicMax per unit into the group head.
        float v = -INFINITY;
        if (lane < 2) {
            float sum = (lane == 0) ? s0 : s1;
            float p = (sum + b) * 0.25f;
            float inner = 0.7978845608f * (p + 0.044715f * p * p * p);
            float g = 0.5f * p * (1.0f + tanhf(inner));
            v = g * 2.0f;
            const bool isHead = ((row0 & (GROUP - 1)) == 0) && (lane == 0);
            if (!isHead) out[row0 + lane] = 0.0f;
        }
        v = fmaxf(v, __shfl_xor_sync(0xFFFFFFFFu, v, 1));
        if (lane == 0) {
            atomicMaxFloat(&out[row0 & ~(GROUP - 1)], v);
        }

        // Consume the prefetched steal.
        u = __shfl_sync(0xFFFFFFFFu, unext, 0);
    }
}

extern "C" void kernel_launch(void* const* d_in, const int* in_sizes, int n_in,
                              void* d_out, int out_size)
{
    const float* x    = (const float*)d_in[0];   // [65536, 2048]
    const float* w    = (const float*)d_in[1];   // [1, 2048]
    const float* bias = (const float*)d_in[2];   // [1]
    float* out = (float*)d_out;                  // [65536]

    init_heads<<<1, NGROUPS>>>(out);
    gemv_phase1<<<NSM, 1024>>>(x, w, bias, out);
}

// round 13
// speedup vs baseline: 1.1306x; 1.1306x over previous
#include <cuda_runtime.h>
#include <math.h>

#define BATCH 65536
#define IN_F  2048
#define GROUP 256
#define VEC_ROW (IN_F / 4)        // 512 float4 per row
#define HALF_V (VEC_ROW / 2)      // 256 float4 per half-row
#define NSM 152
#define NGROUPS (BATCH / GROUP)   // 256
#define MAXR 432                  // max rows per CTA (65536/152 -> 431 or 432)

// float atomic max via signed/unsigned ordering trick (valid for all finite
// floats and -inf init): non-negative -> int max; negative -> uint min.
__device__ __forceinline__ void atomicMaxFloat(float* addr, float v)
{
    if (v >= 0.0f) atomicMax((int*)addr, __float_as_int(v));
    else           atomicMin((unsigned int*)addr, __float_as_uint(v));
}

// -------- Phase 0: init ONLY the 256 group heads to -inf (1 KB) ------------
__global__ __launch_bounds__(NGROUPS)
void init_heads(float* __restrict__ out)
{
    out[threadIdx.x * GROUP] = -INFINITY;
}

// ---------------- Phase 1: half-row units + smem combine --------------------
// Unit = half a row (1KB contiguous). 2R units per CTA over 32 warps gives
// 27.00/26.94 units per warp -> per-warp quantization tail ~0 (vs 0.53 rows
// at row granularity). The two half-partials of a row are combined in CTA
// shared memory; the second finisher runs the GELU epilogue for the row.
__global__ __launch_bounds__(1024, 1)
void gemv_phase1(const float* __restrict__ x,
                 const float* __restrict__ w,
                 const float* __restrict__ bias,
                 float* __restrict__ out)
{
    __shared__ float4   sw[VEC_ROW];   // 8 KB weight cache
    __shared__ float    s_sum[MAXR];   // per-row partial accumulator
    __shared__ unsigned s_cnt[MAXR];   // per-row arrival count

    const int tid  = threadIdx.x;
    const int warp = tid >> 5;
    const int lane = tid & 31;

    if (tid < VEC_ROW) sw[tid] = reinterpret_cast<const float4*>(w)[tid];
    if (tid < MAXR) { s_sum[tid] = 0.0f; s_cnt[tid] = 0u; }
    __syncthreads();

    const float b = bias[0];

    // Contiguous row span per CTA: 431 or 432 rows (65536 over 152 CTAs).
    const int per = BATCH / NSM;            // 431
    const int rem = BATCH % NSM;            // 24
    const int bx  = blockIdx.x;
    const int rbeg = bx * per + (bx < rem ? bx : rem);
    const int R    = per + (bx < rem ? 1 : 0);
    const int U    = 2 * R;                 // half-row units

    for (int u = warp; u < U; u += 32) {
        const int r    = u >> 1;            // local row index
        const int half = u & 1;
        const int row  = rbeg + r;

        const float4* __restrict__ xr =
            reinterpret_cast<const float4*>(x + (size_t)row * IN_F)
            + half * HALF_V + lane;
        const float4* __restrict__ wr = sw + half * HALF_V + lane;

        // 8 independent LDG.128 (4KB/warp, one contiguous 1KB stream per lane
        // stride); two accumulator chains to halve FMA dependency depth.
        float sa = 0.f, sb = 0.f;
        #pragma unroll
        for (int i = 0; i < 8; i += 2) {
            float4 v0 = __ldcs(xr + i * 32);
            float4 v1 = __ldcs(xr + (i + 1) * 32);
            float4 w0 = wr[i * 32];
            float4 w1 = wr[(i + 1) * 32];
            sa = fmaf(v0.x, w0.x, sa); sa = fmaf(v0.y, w0.y, sa);
            sa = fmaf(v0.z, w0.z, sa); sa = fmaf(v0.w, w0.w, sa);
            sb = fmaf(v1.x, w1.x, sb); sb = fmaf(v1.y, w1.y, sb);
            sb = fmaf(v1.z, w1.z, sb); sb = fmaf(v1.w, w1.w, sb);
        }
        float s = sa + sb;

        // Warp all-reduce of the half-row partial.
        #pragma unroll
        for (int o = 16; o > 0; o >>= 1)
            s += __shfl_xor_sync(0xFFFFFFFFu, s, o);

        if (lane == 0) {
            // Publish partial, then arrive. Message-passing order: sum-add ->
            // fence -> cnt-add; the second arriver fences, then reads the
            // completed sum (read via atomicAdd(,0) to defeat reg caching).
            atomicAdd(&s_sum[r], s);
            __threadfence_block();
            if (atomicAdd(&s_cnt[r], 1u) == 1u) {
                __threadfence_block();
                float tot = atomicAdd(&s_sum[r], 0.0f);
                // epilogue: +bias, /4, tanh-GELU, *2
                float p = (tot + b) * 0.25f;
                float inner = 0.7978845608f * (p + 0.044715f * p * p * p);
                float g = 0.5f * p * (1.0f + tanhf(inner));
                float v = g * 2.0f;
                if (row & (GROUP - 1)) out[row] = 0.0f;   // non-head: zero-fill
                atomicMaxFloat(&out[row & ~(GROUP - 1)], v);
            }
        }
    }
}

extern "C" void kernel_launch(void* const* d_in, const int* in_sizes, int n_in,
                              void* d_out, int out_size)
{
    const float* x    = (const float*)d_in[0];   // [65536, 2048]
    const float* w    = (const float*)d_in[1];   // [1, 2048]
    const float* bias = (const float*)d_in[2];   // [1]
    float* out = (float*)d_out;                  // [65536]

    init_heads<<<1, NGROUPS>>>(out);
    gemv_phase1<<<NSM, 1024>>>(x, w, bias, out);
}

// round 14
// speedup vs baseline: 1.2430x; 1.0994x over previous
#include <cuda_runtime.h>
#include <math.h>

#define BATCH 65536
#define IN_F  2048
#define GROUP 256
#define VEC_ROW (IN_F / 4)        // 512 float4 per row
#define KSTEPS  (VEC_ROW / 32)    // 16 float4 per lane per row
#define NSM 152
#define CHUNK 2                   // rows per work unit (fine-grained: small tail)
#define NCHUNKS (BATCH / CHUNK)   // 32768
#define PF 2                      // prefetch distance (3-stage pipeline)
#define NGROUPS (BATCH / GROUP)   // 256

// float atomic max via signed/unsigned ordering trick (valid for all finite
// floats and -inf init): non-negative -> int max; negative -> uint min.
__device__ __forceinline__ void atomicMaxFloat(float* addr, float v)
{
    if (v >= 0.0f) atomicMax((int*)addr, __float_as_int(v));
    else           atomicMin((unsigned int*)addr, __float_as_uint(v));
}

// -------- Phase 0: init ONLY the 256 group heads to -inf (1 KB) ------------
__global__ __launch_bounds__(NGROUPS)
void init_heads(float* __restrict__ out)
{
    out[threadIdx.x * GROUP] = -INFINITY;
}

// ---------------- Phase 1: persistent GEMV + GELU + atomic group max -------
// CHUNK=2: per-warp work = 215/32 ~ 6.7 units, so the end-of-kernel tail
// (warps with one extra unit) is ~0.26 units at ~72% warp liveness, vs
// CHUNK=4's 0.63 units at ~34% liveness. Keeps DRAM subscribed to the end.
__global__ __launch_bounds__(1024, 1)
void gemv_phase1(const float* __restrict__ x,
                 const float* __restrict__ w,
                 const float* __restrict__ bias,
                 float* __restrict__ out)
{
    __shared__ float4 sw[VEC_ROW];   // 8 KB weight cache

    const int tid  = threadIdx.x;
    const int warp = tid >> 5;
    const int lane = tid & 31;

    if (tid < VEC_ROW) sw[tid] = reinterpret_cast<const float4*>(w)[tid];
    __syncthreads();

    const float b = bias[0];

    // Contiguous chunk span per CTA: 215 or 216 chunks (32768 over 152 CTAs).
    const int per = NCHUNKS / NSM;          // 215
    const int rem = NCHUNKS % NSM;          // 88
    const int bx  = blockIdx.x;
    const int begin = bx * per + (bx < rem ? bx : rem);
    const int count = per + (bx < rem ? 1 : 0);

    for (int ci = warp; ci < count; ci += 32) {
        const int row0 = (begin + ci) * CHUNK;
        const float4* __restrict__ xb =
            reinterpret_cast<const float4*>(x + (size_t)row0 * IN_F) + lane;

        float s0 = 0.f, s1 = 0.f;

        // 3-stage software pipeline over 2 rows: ~6 LDG.128 in flight/warp.
        float4 buf[PF + 1][2];
        #pragma unroll
        for (int p = 0; p < PF; p++) {
            const int off = p * 32;
            buf[p][0] = __ldcs(xb + off);
            buf[p][1] = __ldcs(xb + off + VEC_ROW);
        }

        #pragma unroll
        for (int i = 0; i < KSTEPS; i++) {
            if (i + PF < KSTEPS) {
                const int off = (i + PF) * 32;
                const int st  = (i + PF) % (PF + 1);
                buf[st][0] = __ldcs(xb + off);
                buf[st][1] = __ldcs(xb + off + VEC_ROW);
            }
            const int cu = i % (PF + 1);
            float4 wv = sw[lane + i * 32];
            s0 = fmaf(buf[cu][0].x, wv.x, s0); s0 = fmaf(buf[cu][0].y, wv.y, s0);
            s0 = fmaf(buf[cu][0].z, wv.z, s0); s0 = fmaf(buf[cu][0].w, wv.w, s0);
            s1 = fmaf(buf[cu][1].x, wv.x, s1); s1 = fmaf(buf[cu][1].y, wv.y, s1);
            s1 = fmaf(buf[cu][1].z, wv.z, s1); s1 = fmaf(buf[cu][1].w, wv.w, s1);
        }

        // 2 interleaved butterfly all-reduces.
        #pragma unroll
        for (int o = 16; o > 0; o >>= 1) {
            s0 += __shfl_xor_sync(0xFFFFFFFFu, s0, o);
            s1 += __shfl_xor_sync(0xFFFFFFFFu, s1, o);
        }

        // Epilogue: lanes 0..1 compute the 2 row GELUs; zero-fill non-head
        // rows; one atomicMax per chunk into the group head.
        float v = -INFINITY;
        if (lane < 2) {
            float sum = (lane == 0) ? s0 : s1;
            float p = (sum + b) * 0.25f;
            float inner = 0.7978845608f * (p + 0.044715f * p * p * p);
            float g = 0.5f * p * (1.0f + tanhf(inner));
            v = g * 2.0f;
            const bool isHead = ((row0 & (GROUP - 1)) == 0) && (lane == 0);
            if (!isHead) out[row0 + lane] = 0.0f;
        }
        v = fmaxf(v, __shfl_xor_sync(0xFFFFFFFFu, v, 1));
        if (lane == 0) {
            atomicMaxFloat(&out[row0 & ~(GROUP - 1)], v);
        }
    }
}

extern "C" void kernel_launch(void* const* d_in, const int* in_sizes, int n_in,
                              void* d_out, int out_size)
{
    const float* x    = (const float*)d_in[0];   // [65536, 2048]
    const float* w    = (const float*)d_in[1];   // [1, 2048]
    const float* bias = (const float*)d_in[2];   // [1]
    float* out = (float*)d_out;                  // [65536]

    init_heads<<<1, NGROUPS>>>(out);
    gemv_phase1<<<NSM, 1024>>>(x, w, bias, out);
}